// round 3
// baseline (speedup 1.0000x reference)
#include <cuda_runtime.h>
#include <cuda_bf16.h>
#include <cstdint>

typedef unsigned long long ull;

#define SQ   4096
#define DIM  768
#define HID  384
#define G4   1536
#define NEV  1024

// ---------------- static scratch (no runtime allocation) ----------------
__device__ float g_xw[2u * SQ * G4];    // permuted gate preactivations, both dirs
__device__ float g_tok[(size_t)SQ * DIM];
__device__ float g_emb[NEV * DIM];
__device__ float g_hidn[NEV * DIM];
__device__ float g_evloss[NEV];
__device__ float g_h[2 * 2 * HID];      // [buf][dir][HID]
__device__ int   g_flags[32];           // 16 fwd + 16 bwd step counters
__device__ float g_scores_scratch[2 * NEV];
__device__ float g_loss_scratch[1];

__global__ void init_kernel() {
    if (threadIdx.x < 32) g_flags[threadIdx.x] = 0;
}

__device__ __forceinline__ float sigmoid_f(float x) { return 1.0f / (1.0f + expf(-x)); }

// ---------------------------------------------------------------------------
// GEMM A: xw[d][t][jj] = X[t] . W_d[orig(jj)] + (bih+bhh)[orig]
// column permutation: jj = cta*96 + gate*24 + u  <->  orig = gate*384 + cta*24 + u
// 64x64 tile, BK=32, 256 threads, 4x4/thread, packed fma.rn.f32x2
// ---------------------------------------------------------------------------
__global__ __launch_bounds__(256) void gemm_xw_kernel(
    const float* __restrict__ X,
    const float* __restrict__ Wf, const float* __restrict__ Wb,
    const float* __restrict__ bihf, const float* __restrict__ bhhf,
    const float* __restrict__ bihb, const float* __restrict__ bhhb)
{
    __shared__ float As[32][72];
    __shared__ float Bs[32][72];
    __shared__ const float* wptr[64];
    __shared__ float biasv[64];

    int tid = threadIdx.x;
    int bx = blockIdx.x, by = blockIdx.y;

    if (tid < 64) {
        int jp = bx * 64 + tid;          // 0..3071
        int d  = jp / G4;
        int jj = jp - d * G4;
        int cc = jj / 96, ll = jj % 96;
        int orig = (ll / 24) * HID + cc * 24 + (ll % 24);
        wptr[tid]  = (d ? Wb : Wf) + (size_t)orig * DIM;
        biasv[tid] = d ? (bihb[orig] + bhhb[orig]) : (bihf[orig] + bhhf[orig]);
    }
    __syncthreads();

    int tx = tid & 15, ty = tid >> 4;
    ull acc2[4][2];
    #pragma unroll
    for (int i = 0; i < 4; i++) { acc2[i][0] = 0ull; acc2[i][1] = 0ull; }

    for (int k0 = 0; k0 < DIM; k0 += 32) {
        #pragma unroll
        for (int i = 0; i < 2; i++) {
            int id = tid + i * 256;
            int r = id >> 3, c4 = id & 7;
            float4 v = *reinterpret_cast<const float4*>(X + (size_t)(by * 64 + r) * DIM + k0 + c4 * 4);
            As[c4*4+0][r] = v.x; As[c4*4+1][r] = v.y; As[c4*4+2][r] = v.z; As[c4*4+3][r] = v.w;
            float4 w = *reinterpret_cast<const float4*>(wptr[r] + k0 + c4 * 4);
            Bs[c4*4+0][r] = w.x; Bs[c4*4+1][r] = w.y; Bs[c4*4+2][r] = w.z; Bs[c4*4+3][r] = w.w;
        }
        __syncthreads();
        #pragma unroll
        for (int k = 0; k < 32; k++) {
            float4 av = *reinterpret_cast<const float4*>(&As[k][ty * 4]);
            ull b0 = *reinterpret_cast<const ull*>(&Bs[k][tx * 4]);
            ull b1 = *reinterpret_cast<const ull*>(&Bs[k][tx * 4 + 2]);
            float a_[4] = {av.x, av.y, av.z, av.w};
            #pragma unroll
            for (int i = 0; i < 4; i++) {
                ull ad;
                asm("mov.b64 %0, {%1, %1};" : "=l"(ad) : "f"(a_[i]));
                asm("fma.rn.f32x2 %0, %1, %2, %0;" : "+l"(acc2[i][0]) : "l"(ad), "l"(b0));
                asm("fma.rn.f32x2 %0, %1, %2, %0;" : "+l"(acc2[i][1]) : "l"(ad), "l"(b1));
            }
        }
        __syncthreads();
    }

    int d = (bx * 64) / G4;
    size_t outbase = (size_t)d * SQ * G4;
    int col0 = bx * 64 - d * G4 + tx * 4;
    #pragma unroll
    for (int i = 0; i < 4; i++) {
        int t = by * 64 + ty * 4 + i;
        float2 p0 = *reinterpret_cast<float2*>(&acc2[i][0]);
        float2 p1 = *reinterpret_cast<float2*>(&acc2[i][1]);
        float* o = g_xw + outbase + (size_t)t * G4 + col0;
        o[0] = p0.x + biasv[tx*4+0];
        o[1] = p0.y + biasv[tx*4+1];
        o[2] = p1.x + biasv[tx*4+2];
        o[3] = p1.y + biasv[tx*4+3];
    }
}

// ---------------------------------------------------------------------------
// LSTM: 32 CTAs (16/direction), 384 threads, weights register-resident.
// CTA owns 24 hidden units; thread tid handles row rr=tid>>2 (gate*24+u),
// k-chunk q=tid&3 (96 of 384 h-values). Global h exchange, double-buffered.
// ---------------------------------------------------------------------------
__global__ __launch_bounds__(384, 1) void lstm_kernel(
    const float* __restrict__ Whh_f, const float* __restrict__ Whh_b)
{
    __shared__ float sh_h[4 * 98];      // padded chunks: chunk q at q*98
    __shared__ float sh_gate[96];

    int tid = threadIdx.x;
    int dir = blockIdx.x >> 4;
    int cta = blockIdx.x & 15;
    int rr = tid >> 2, q = tid & 3;
    int gate = rr / 24, u = rr % 24;
    int orig = gate * HID + cta * 24 + u;

    const float* Whh = dir ? Whh_b : Whh_f;
    const ull* wrow = reinterpret_cast<const ull*>(Whh + (size_t)orig * HID + q * 96);
    ull wreg[48];
    #pragma unroll
    for (int j = 0; j < 48; j++) wreg[j] = wrow[j];

    for (int i = tid; i < 4 * 98; i += 384) sh_h[i] = 0.0f;

    const float* xwp = g_xw + (size_t)dir * SQ * G4 + cta * 96 + rr;
    float c_reg = 0.0f;
    __syncthreads();

    const ull* hp = reinterpret_cast<const ull*>(sh_h + q * 98);
    int* myflag = g_flags + dir * 16 + cta;
    int* pollflag = g_flags + dir * 16 + (tid & 15);

    for (int t = 0; t < SQ; t++) {
        int tt = dir ? (SQ - 1 - t) : t;
        float xwv = (q == 0) ? __ldcg(xwp + (size_t)tt * G4) : 0.0f;

        ull acc = 0ull;
        #pragma unroll
        for (int j = 0; j < 48; j++)
            asm("fma.rn.f32x2 %0, %1, %2, %0;" : "+l"(acc) : "l"(wreg[j]), "l"(hp[j]));
        float lo, hi;
        asm("mov.b64 {%0, %1}, %2;" : "=f"(lo), "=f"(hi) : "l"(acc));
        float s = lo + hi;
        s += __shfl_xor_sync(0xffffffffu, s, 1);
        s += __shfl_xor_sync(0xffffffffu, s, 2);
        if (q == 0) sh_gate[rr] = s + xwv;
        __syncthreads();

        if (tid < 24) {
            float gi = sh_gate[tid], gf = sh_gate[24 + tid];
            float gg = sh_gate[48 + tid], go = sh_gate[72 + tid];
            float cf = sigmoid_f(gf) * c_reg + sigmoid_f(gi) * tanhf(gg);
            c_reg = cf;
            float hv = sigmoid_f(go) * tanhf(cf);
            int hidx = cta * 24 + tid;
            g_h[(t & 1) * 2 * HID + dir * HID + hidx] = hv;
            g_tok[(size_t)tt * DIM + dir * HID + hidx] = hv;
        }
        __threadfence();
        __syncthreads();
        if (tid == 0) {
            asm volatile("st.release.gpu.global.s32 [%0], %1;"
                         :: "l"(myflag), "r"(t + 1) : "memory");
        }
        if (tid < 16) {
            int v;
            do {
                asm volatile("ld.acquire.gpu.global.s32 %0, [%1];"
                             : "=r"(v) : "l"(pollflag) : "memory");
            } while (v <= t);
        }
        __syncthreads();
        if (tid < 96) {
            float4 hv = __ldcg(reinterpret_cast<const float4*>(g_h + (t & 1) * 2 * HID + dir * HID) + tid);
            int base = (tid / 24) * 98 + (tid % 24) * 4;
            sh_h[base + 0] = hv.x; sh_h[base + 1] = hv.y;
            sh_h[base + 2] = hv.z; sh_h[base + 3] = hv.w;
        }
        __syncthreads();
    }
}

// ---------------------------------------------------------------------------
// Event mean-pool: one CTA per event
// ---------------------------------------------------------------------------
__global__ __launch_bounds__(256) void pool_kernel(const int* __restrict__ label_event)
{
    int e = blockIdx.x;
    int start = label_event[e * 3 + 0];
    int end   = label_event[e * 3 + 1];
    float inv = 1.0f / (float)(end - start);
    for (int c = threadIdx.x; c < DIM; c += 256) {
        float s = 0.0f;
        for (int r = start; r < end; r++) s += g_tok[(size_t)r * DIM + c];
        g_emb[(size_t)e * DIM + c] = s * inv;
    }
}

// ---------------------------------------------------------------------------
// MLP layer 1: hid = relu(emb @ W1^T + b1)   [1024 x 768] x [768 x 768]
// ---------------------------------------------------------------------------
__global__ __launch_bounds__(256) void gemm_mlp1_kernel(
    const float* __restrict__ W1, const float* __restrict__ b1)
{
    __shared__ float As[32][72];
    __shared__ float Bs[32][72];

    int tid = threadIdx.x;
    int bx = blockIdx.x, by = blockIdx.y;
    int tx = tid & 15, ty = tid >> 4;

    ull acc2[4][2];
    #pragma unroll
    for (int i = 0; i < 4; i++) { acc2[i][0] = 0ull; acc2[i][1] = 0ull; }

    for (int k0 = 0; k0 < DIM; k0 += 32) {
        #pragma unroll
        for (int i = 0; i < 2; i++) {
            int id = tid + i * 256;
            int r = id >> 3, c4 = id & 7;
            float4 v = *reinterpret_cast<const float4*>(g_emb + (size_t)(by * 64 + r) * DIM + k0 + c4 * 4);
            As[c4*4+0][r] = v.x; As[c4*4+1][r] = v.y; As[c4*4+2][r] = v.z; As[c4*4+3][r] = v.w;
            float4 w = *reinterpret_cast<const float4*>(W1 + (size_t)(bx * 64 + r) * DIM + k0 + c4 * 4);
            Bs[c4*4+0][r] = w.x; Bs[c4*4+1][r] = w.y; Bs[c4*4+2][r] = w.z; Bs[c4*4+3][r] = w.w;
        }
        __syncthreads();
        #pragma unroll
        for (int k = 0; k < 32; k++) {
            float4 av = *reinterpret_cast<const float4*>(&As[k][ty * 4]);
            ull b0 = *reinterpret_cast<const ull*>(&Bs[k][tx * 4]);
            ull b1v = *reinterpret_cast<const ull*>(&Bs[k][tx * 4 + 2]);
            float a_[4] = {av.x, av.y, av.z, av.w};
            #pragma unroll
            for (int i = 0; i < 4; i++) {
                ull ad;
                asm("mov.b64 %0, {%1, %1};" : "=l"(ad) : "f"(a_[i]));
                asm("fma.rn.f32x2 %0, %1, %2, %0;" : "+l"(acc2[i][0]) : "l"(ad), "l"(b0));
                asm("fma.rn.f32x2 %0, %1, %2, %0;" : "+l"(acc2[i][1]) : "l"(ad), "l"(b1v));
            }
        }
        __syncthreads();
    }

    int col0 = bx * 64 + tx * 4;
    #pragma unroll
    for (int i = 0; i < 4; i++) {
        int row = by * 64 + ty * 4 + i;
        float2 p0 = *reinterpret_cast<float2*>(&acc2[i][0]);
        float2 p1 = *reinterpret_cast<float2*>(&acc2[i][1]);
        float* o = g_hidn + (size_t)row * DIM + col0;
        o[0] = fmaxf(p0.x + b1[col0 + 0], 0.0f);
        o[1] = fmaxf(p0.y + b1[col0 + 1], 0.0f);
        o[2] = fmaxf(p1.x + b1[col0 + 2], 0.0f);
        o[3] = fmaxf(p1.y + b1[col0 + 3], 0.0f);
    }
}

// ---------------------------------------------------------------------------
// Layer 2 + log-softmax + weighted CE per event. One warp per event.
// ---------------------------------------------------------------------------
__global__ __launch_bounds__(256) void scores_kernel(
    const float* __restrict__ W2, const float* __restrict__ b2,
    const int* __restrict__ label_event, float* scores_out)
{
    int lane = threadIdx.x & 31;
    int w = threadIdx.x >> 5;
    int e = blockIdx.x * 8 + w;
    const float* hrow = g_hidn + (size_t)e * DIM;

    float s0 = 0.0f, s1 = 0.0f;
    #pragma unroll
    for (int k = 0; k < 24; k++) {
        float v = hrow[lane + 32 * k];
        s0 += v * __ldg(&W2[lane + 32 * k]);
        s1 += v * __ldg(&W2[DIM + lane + 32 * k]);
    }
    #pragma unroll
    for (int m = 16; m >= 1; m >>= 1) {
        s0 += __shfl_xor_sync(0xffffffffu, s0, m);
        s1 += __shfl_xor_sync(0xffffffffu, s1, m);
    }
    if (lane == 0) {
        s0 += b2[0]; s1 += b2[1];
        float* sp = scores_out ? scores_out : g_scores_scratch;
        sp[2 * e + 0] = s0;
        sp[2 * e + 1] = s1;
        float mx = fmaxf(s0, s1);
        float lse = mx + logf(expf(s0 - mx) + expf(s1 - mx));
        int lab = label_event[e * 3 + 2];
        float sl = lab ? s1 : s0;
        float ce = lse - sl;
        float wgt = (lab == 0) ? 1.0f : (float)lab * 1.0f;
        g_evloss[e] = ce * wgt;
    }
}

__global__ __launch_bounds__(1024) void loss_reduce_kernel(float* loss_out)
{
    __shared__ float red[1024];
    int tid = threadIdx.x;
    red[tid] = g_evloss[tid];
    __syncthreads();
    for (int s = 512; s >= 1; s >>= 1) {
        if (tid < s) red[tid] += red[tid + s];
        __syncthreads();
    }
    if (tid == 0) {
        float* lp = loss_out ? loss_out : g_loss_scratch;
        lp[0] = red[0];
    }
}

// ---------------------------------------------------------------------------
extern "C" void kernel_launch(void* const* d_in, const int* in_sizes, int n_in,
                              void* d_out, int out_size) {
    const float* X     = (const float*)d_in[0];
    const int*   lev   = (const int*)  d_in[1];
    const float* Wih_f = (const float*)d_in[2];
    const float* Whh_f = (const float*)d_in[3];
    const float* bih_f = (const float*)d_in[4];
    const float* bhh_f = (const float*)d_in[5];
    const float* Wih_b = (const float*)d_in[6];
    const float* Whh_b = (const float*)d_in[7];
    const float* bih_b = (const float*)d_in[8];
    const float* bhh_b = (const float*)d_in[9];
    const float* W1    = (const float*)d_in[10];
    const float* b1    = (const float*)d_in[11];
    const float* W2    = (const float*)d_in[12];
    const float* b2    = (const float*)d_in[13];

    float* out = (float*)d_out;
    float* loss_ptr   = nullptr;
    float* scores_ptr = nullptr;
    if (out_size >= 2049)      { loss_ptr = out; scores_ptr = out + 1; }
    else if (out_size >= 2048) { scores_ptr = out; }
    else                       { loss_ptr = out; }

    init_kernel<<<1, 32>>>();
    gemm_xw_kernel<<<dim3(48, 64), 256>>>(X, Wih_f, Wih_b, bih_f, bhh_f, bih_b, bhh_b);
    lstm_kernel<<<32, 384>>>(Whh_f, Whh_b);
    pool_kernel<<<NEV, 256>>>(lev);
    gemm_mlp1_kernel<<<dim3(12, 16), 256>>>(W1, b1);
    scores_kernel<<<NEV / 8, 256>>>(W2, b2, lev, scores_ptr);
    loss_reduce_kernel<<<1, 1024>>>(loss_ptr);
}

// round 4
// speedup vs baseline: 2.2419x; 2.2419x over previous
#include <cuda_runtime.h>
#include <cuda_bf16.h>
#include <cstdint>

typedef unsigned long long ull;

#define SQ   4096
#define DIM  768
#define HID  384
#define G4   1536
#define NEV  1024

// ---------------- static scratch (no runtime allocation) ----------------
__device__ float g_xw[2u * SQ * G4];    // permuted gate preactivations, both dirs
__device__ float g_tok[(size_t)SQ * DIM];
__device__ float g_emb[NEV * DIM];
__device__ float g_hidn[NEV * DIM];
__device__ float g_evloss[NEV];
__device__ float g_scores_scratch[2 * NEV];
__device__ float g_loss_scratch[1];

__device__ __forceinline__ float sigmoid_f(float x) { return 1.0f / (1.0f + expf(-x)); }

__device__ __forceinline__ unsigned smem_u32(const void* p) {
    unsigned a;
    asm("{ .reg .u64 t; cvta.to.shared.u64 t, %1; cvt.u32.u64 %0, t; }" : "=r"(a) : "l"(p));
    return a;
}

// ---------------------------------------------------------------------------
// GEMM A: xw[d][t][jj] = X[t] . W_d[orig(jj)] + (bih+bhh)[orig]
// column permutation: jj = cta*96 + gate*24 + u  <->  orig = gate*384 + cta*24 + u
// 64x64 tile, BK=32, 256 threads, 4x4/thread, packed fma.rn.f32x2
// ---------------------------------------------------------------------------
__global__ __launch_bounds__(256) void gemm_xw_kernel(
    const float* __restrict__ X,
    const float* __restrict__ Wf, const float* __restrict__ Wb,
    const float* __restrict__ bihf, const float* __restrict__ bhhf,
    const float* __restrict__ bihb, const float* __restrict__ bhhb)
{
    __shared__ float As[32][72];
    __shared__ float Bs[32][72];
    __shared__ const float* wptr[64];
    __shared__ float biasv[64];

    int tid = threadIdx.x;
    int bx = blockIdx.x, by = blockIdx.y;

    if (tid < 64) {
        int jp = bx * 64 + tid;          // 0..3071
        int d  = jp / G4;
        int jj = jp - d * G4;
        int cc = jj / 96, ll = jj % 96;
        int orig = (ll / 24) * HID + cc * 24 + (ll % 24);
        wptr[tid]  = (d ? Wb : Wf) + (size_t)orig * DIM;
        biasv[tid] = d ? (bihb[orig] + bhhb[orig]) : (bihf[orig] + bhhf[orig]);
    }
    __syncthreads();

    int tx = tid & 15, ty = tid >> 4;
    ull acc2[4][2];
    #pragma unroll
    for (int i = 0; i < 4; i++) { acc2[i][0] = 0ull; acc2[i][1] = 0ull; }

    for (int k0 = 0; k0 < DIM; k0 += 32) {
        #pragma unroll
        for (int i = 0; i < 2; i++) {
            int id = tid + i * 256;
            int r = id >> 3, c4 = id & 7;
            float4 v = *reinterpret_cast<const float4*>(X + (size_t)(by * 64 + r) * DIM + k0 + c4 * 4);
            As[c4*4+0][r] = v.x; As[c4*4+1][r] = v.y; As[c4*4+2][r] = v.z; As[c4*4+3][r] = v.w;
            float4 w = *reinterpret_cast<const float4*>(wptr[r] + k0 + c4 * 4);
            Bs[c4*4+0][r] = w.x; Bs[c4*4+1][r] = w.y; Bs[c4*4+2][r] = w.z; Bs[c4*4+3][r] = w.w;
        }
        __syncthreads();
        #pragma unroll
        for (int k = 0; k < 32; k++) {
            float4 av = *reinterpret_cast<const float4*>(&As[k][ty * 4]);
            ull b0 = *reinterpret_cast<const ull*>(&Bs[k][tx * 4]);
            ull b1 = *reinterpret_cast<const ull*>(&Bs[k][tx * 4 + 2]);
            float a_[4] = {av.x, av.y, av.z, av.w};
            #pragma unroll
            for (int i = 0; i < 4; i++) {
                ull ad;
                asm("mov.b64 %0, {%1, %1};" : "=l"(ad) : "f"(a_[i]));
                asm("fma.rn.f32x2 %0, %1, %2, %0;" : "+l"(acc2[i][0]) : "l"(ad), "l"(b0));
                asm("fma.rn.f32x2 %0, %1, %2, %0;" : "+l"(acc2[i][1]) : "l"(ad), "l"(b1));
            }
        }
        __syncthreads();
    }

    int d = (bx * 64) / G4;
    size_t outbase = (size_t)d * SQ * G4;
    int col0 = bx * 64 - d * G4 + tx * 4;
    #pragma unroll
    for (int i = 0; i < 4; i++) {
        int t = by * 64 + ty * 4 + i;
        float2 p0 = *reinterpret_cast<float2*>(&acc2[i][0]);
        float2 p1 = *reinterpret_cast<float2*>(&acc2[i][1]);
        float* o = g_xw + outbase + (size_t)t * G4 + col0;
        o[0] = p0.x + biasv[tx*4+0];
        o[1] = p0.y + biasv[tx*4+1];
        o[2] = p1.x + biasv[tx*4+2];
        o[3] = p1.y + biasv[tx*4+3];
    }
}

// ---------------------------------------------------------------------------
// LSTM: one 16-CTA cluster per direction. Weights register-resident
// (96 fp32/thread). h exchanged by DSMEM push: each CTA's 24 new h values
// are stored directly into every peer's double-buffered SMEM (one
// st.shared::cluster per thread: 384 threads = 24 units x 16 peers),
// then one cluster barrier per step (release/acquire).
// MAC role: rr = tid>>2 (row 0..95), q = tid&3 (96-wide k-chunk).
// Activation role: u = tid%24 (unit), peer = tid/24; c-state replicated 16x.
// ---------------------------------------------------------------------------
__global__ __launch_bounds__(384, 1) void lstm_kernel(
    const float* __restrict__ Whh_f, const float* __restrict__ Whh_b)
{
    __shared__ __align__(16) float sh_h[2 * 400];   // [buf][chunk q at q*100]
    __shared__ float sh_gate[96];

    int tid = threadIdx.x;
    int dir = blockIdx.x >> 4;
    unsigned cta;
    asm("mov.u32 %0, %%cluster_ctarank;" : "=r"(cta));

    int rr = tid >> 2, q = tid & 3;
    int u = tid % 24, peer = tid / 24;
    int gate = rr / 24, uu = rr % 24;
    int orig = gate * HID + (int)cta * 24 + uu;

    const float* Whh = dir ? Whh_b : Whh_f;
    const ull* wrow = reinterpret_cast<const ull*>(Whh + (size_t)orig * HID + q * 96);
    ull wreg[48];
    #pragma unroll
    for (int j = 0; j < 48; j++) wreg[j] = wrow[j];

    // zero both h buffers
    for (int i = tid; i < 2 * 400; i += 384) sh_h[i] = 0.0f;

    // DSMEM target addresses for my unit hidx in peer's buffers
    int hidx = (int)cta * 24 + u;
    int qq = hidx / 96, mm = hidx % 96;
    unsigned loc0 = smem_u32(&sh_h[qq * 100 + mm]);
    unsigned loc1 = loc0 + 400 * 4;
    unsigned rem0, rem1;
    asm("mapa.shared::cluster.u32 %0, %1, %2;" : "=r"(rem0) : "r"(loc0), "r"(peer));
    asm("mapa.shared::cluster.u32 %0, %1, %2;" : "=r"(rem1) : "r"(loc1), "r"(peer));

    // all buffers zeroed cluster-wide before any DSMEM store
    asm volatile("barrier.cluster.arrive.aligned;" ::: "memory");
    asm volatile("barrier.cluster.wait.aligned;"   ::: "memory");

    const float* xwp = g_xw + (size_t)dir * SQ * G4 + (size_t)cta * 96 + rr;
    float c_reg = 0.0f;
    float xw_cur = (q == 0) ? __ldcg(xwp + (size_t)(dir ? SQ - 1 : 0) * G4) : 0.0f;

    for (int t = 0; t < SQ; t++) {
        int par = t & 1;

        // prefetch next step's xw (covers L2 latency with this whole step)
        float xw_next = 0.0f;
        if (q == 0 && t + 1 < SQ) {
            int tn = dir ? (SQ - 2 - t) : (t + 1);
            xw_next = __ldcg(xwp + (size_t)tn * G4);
        }

        // MAC: this row's 96-element k-chunk of h
        const ulonglong2* hp2 =
            reinterpret_cast<const ulonglong2*>(sh_h + par * 400 + q * 100);
        ull a0 = 0ull, a1 = 0ull, a2 = 0ull, a3 = 0ull;
        #pragma unroll
        for (int j = 0; j < 12; j++) {
            ulonglong2 x0 = hp2[2 * j];
            ulonglong2 x1 = hp2[2 * j + 1];
            asm("fma.rn.f32x2 %0, %1, %2, %0;" : "+l"(a0) : "l"(wreg[4*j+0]), "l"(x0.x));
            asm("fma.rn.f32x2 %0, %1, %2, %0;" : "+l"(a1) : "l"(wreg[4*j+1]), "l"(x0.y));
            asm("fma.rn.f32x2 %0, %1, %2, %0;" : "+l"(a2) : "l"(wreg[4*j+2]), "l"(x1.x));
            asm("fma.rn.f32x2 %0, %1, %2, %0;" : "+l"(a3) : "l"(wreg[4*j+3]), "l"(x1.y));
        }
        asm("add.rn.f32x2 %0, %0, %1;" : "+l"(a0) : "l"(a1));
        asm("add.rn.f32x2 %0, %0, %1;" : "+l"(a2) : "l"(a3));
        asm("add.rn.f32x2 %0, %0, %1;" : "+l"(a0) : "l"(a2));
        float lo, hi;
        asm("mov.b64 {%0, %1}, %2;" : "=f"(lo), "=f"(hi) : "l"(a0));
        float s = lo + hi;
        s += __shfl_xor_sync(0xffffffffu, s, 1);
        s += __shfl_xor_sync(0xffffffffu, s, 2);
        if (q == 0) sh_gate[rr] = s + xw_cur;
        __syncthreads();

        // activation (replicated across the 16 peer-groups, deterministic)
        float gi = sh_gate[u], gf = sh_gate[24 + u];
        float gg = sh_gate[48 + u], go = sh_gate[72 + u];
        float cf = sigmoid_f(gf) * c_reg + sigmoid_f(gi) * tanhf(gg);
        c_reg = cf;
        float hv = sigmoid_f(go) * tanhf(cf);

        // push my unit's h into peer's buf[(t+1)&1]
        unsigned rem = par ? rem0 : rem1;
        asm volatile("st.shared::cluster.f32 [%0], %1;" :: "r"(rem), "f"(hv) : "memory");

        if (peer == 0) {
            int tt = dir ? (SQ - 1 - t) : t;
            g_tok[(size_t)tt * DIM + dir * HID + hidx] = hv;
        }

        asm volatile("barrier.cluster.arrive.aligned;" ::: "memory");
        asm volatile("barrier.cluster.wait.aligned;"   ::: "memory");

        xw_cur = xw_next;
    }
}

// ---------------------------------------------------------------------------
// Event mean-pool: one CTA per event
// ---------------------------------------------------------------------------
__global__ __launch_bounds__(256) void pool_kernel(const int* __restrict__ label_event)
{
    int e = blockIdx.x;
    int start = label_event[e * 3 + 0];
    int end   = label_event[e * 3 + 1];
    float inv = 1.0f / (float)(end - start);
    for (int c = threadIdx.x; c < DIM; c += 256) {
        float s = 0.0f;
        for (int r = start; r < end; r++) s += g_tok[(size_t)r * DIM + c];
        g_emb[(size_t)e * DIM + c] = s * inv;
    }
}

// ---------------------------------------------------------------------------
// MLP layer 1: hid = relu(emb @ W1^T + b1)   [1024 x 768] x [768 x 768]
// ---------------------------------------------------------------------------
__global__ __launch_bounds__(256) void gemm_mlp1_kernel(
    const float* __restrict__ W1, const float* __restrict__ b1)
{
    __shared__ float As[32][72];
    __shared__ float Bs[32][72];

    int tid = threadIdx.x;
    int bx = blockIdx.x, by = blockIdx.y;
    int tx = tid & 15, ty = tid >> 4;

    ull acc2[4][2];
    #pragma unroll
    for (int i = 0; i < 4; i++) { acc2[i][0] = 0ull; acc2[i][1] = 0ull; }

    for (int k0 = 0; k0 < DIM; k0 += 32) {
        #pragma unroll
        for (int i = 0; i < 2; i++) {
            int id = tid + i * 256;
            int r = id >> 3, c4 = id & 7;
            float4 v = *reinterpret_cast<const float4*>(g_emb + (size_t)(by * 64 + r) * DIM + k0 + c4 * 4);
            As[c4*4+0][r] = v.x; As[c4*4+1][r] = v.y; As[c4*4+2][r] = v.z; As[c4*4+3][r] = v.w;
            float4 w = *reinterpret_cast<const float4*>(W1 + (size_t)(bx * 64 + r) * DIM + k0 + c4 * 4);
            Bs[c4*4+0][r] = w.x; Bs[c4*4+1][r] = w.y; Bs[c4*4+2][r] = w.z; Bs[c4*4+3][r] = w.w;
        }
        __syncthreads();
        #pragma unroll
        for (int k = 0; k < 32; k++) {
            float4 av = *reinterpret_cast<const float4*>(&As[k][ty * 4]);
            ull b0 = *reinterpret_cast<const ull*>(&Bs[k][tx * 4]);
            ull b1v = *reinterpret_cast<const ull*>(&Bs[k][tx * 4 + 2]);
            float a_[4] = {av.x, av.y, av.z, av.w};
            #pragma unroll
            for (int i = 0; i < 4; i++) {
                ull ad;
                asm("mov.b64 %0, {%1, %1};" : "=l"(ad) : "f"(a_[i]));
                asm("fma.rn.f32x2 %0, %1, %2, %0;" : "+l"(acc2[i][0]) : "l"(ad), "l"(b0));
                asm("fma.rn.f32x2 %0, %1, %2, %0;" : "+l"(acc2[i][1]) : "l"(ad), "l"(b1v));
            }
        }
        __syncthreads();
    }

    int col0 = bx * 64 + tx * 4;
    #pragma unroll
    for (int i = 0; i < 4; i++) {
        int row = by * 64 + ty * 4 + i;
        float2 p0 = *reinterpret_cast<float2*>(&acc2[i][0]);
        float2 p1 = *reinterpret_cast<float2*>(&acc2[i][1]);
        float* o = g_hidn + (size_t)row * DIM + col0;
        o[0] = fmaxf(p0.x + b1[col0 + 0], 0.0f);
        o[1] = fmaxf(p0.y + b1[col0 + 1], 0.0f);
        o[2] = fmaxf(p1.x + b1[col0 + 2], 0.0f);
        o[3] = fmaxf(p1.y + b1[col0 + 3], 0.0f);
    }
}

// ---------------------------------------------------------------------------
// Layer 2 + log-softmax + weighted CE per event. One warp per event.
// ---------------------------------------------------------------------------
__global__ __launch_bounds__(256) void scores_kernel(
    const float* __restrict__ W2, const float* __restrict__ b2,
    const int* __restrict__ label_event, float* scores_out)
{
    int lane = threadIdx.x & 31;
    int w = threadIdx.x >> 5;
    int e = blockIdx.x * 8 + w;
    const float* hrow = g_hidn + (size_t)e * DIM;

    float s0 = 0.0f, s1 = 0.0f;
    #pragma unroll
    for (int k = 0; k < 24; k++) {
        float v = hrow[lane + 32 * k];
        s0 += v * __ldg(&W2[lane + 32 * k]);
        s1 += v * __ldg(&W2[DIM + lane + 32 * k]);
    }
    #pragma unroll
    for (int m = 16; m >= 1; m >>= 1) {
        s0 += __shfl_xor_sync(0xffffffffu, s0, m);
        s1 += __shfl_xor_sync(0xffffffffu, s1, m);
    }
    if (lane == 0) {
        s0 += b2[0]; s1 += b2[1];
        float* sp = scores_out ? scores_out : g_scores_scratch;
        sp[2 * e + 0] = s0;
        sp[2 * e + 1] = s1;
        float mx = fmaxf(s0, s1);
        float lse = mx + logf(expf(s0 - mx) + expf(s1 - mx));
        int lab = label_event[e * 3 + 2];
        float sl = lab ? s1 : s0;
        float ce = lse - sl;
        float wgt = (lab == 0) ? 1.0f : (float)lab * 1.0f;
        g_evloss[e] = ce * wgt;
    }
}

__global__ __launch_bounds__(1024) void loss_reduce_kernel(float* loss_out)
{
    __shared__ float red[1024];
    int tid = threadIdx.x;
    red[tid] = g_evloss[tid];
    __syncthreads();
    for (int s = 512; s >= 1; s >>= 1) {
        if (tid < s) red[tid] += red[tid + s];
        __syncthreads();
    }
    if (tid == 0) {
        float* lp = loss_out ? loss_out : g_loss_scratch;
        lp[0] = red[0];
    }
}

// ---------------------------------------------------------------------------
extern "C" void kernel_launch(void* const* d_in, const int* in_sizes, int n_in,
                              void* d_out, int out_size) {
    const float* X     = (const float*)d_in[0];
    const int*   lev   = (const int*)  d_in[1];
    const float* Wih_f = (const float*)d_in[2];
    const float* Whh_f = (const float*)d_in[3];
    const float* bih_f = (const float*)d_in[4];
    const float* bhh_f = (const float*)d_in[5];
    const float* Wih_b = (const float*)d_in[6];
    const float* Whh_b = (const float*)d_in[7];
    const float* bih_b = (const float*)d_in[8];
    const float* bhh_b = (const float*)d_in[9];
    const float* W1    = (const float*)d_in[10];
    const float* b1    = (const float*)d_in[11];
    const float* W2    = (const float*)d_in[12];
    const float* b2    = (const float*)d_in[13];

    float* out = (float*)d_out;
    float* loss_ptr   = nullptr;
    float* scores_ptr = nullptr;
    if (out_size >= 2049)      { loss_ptr = out; scores_ptr = out + 1; }
    else if (out_size >= 2048) { scores_ptr = out; }
    else                       { loss_ptr = out; }

    gemm_xw_kernel<<<dim3(48, 64), 256>>>(X, Wih_f, Wih_b, bih_f, bhh_f, bih_b, bhh_b);

    // LSTM: 2 clusters of 16 CTAs (non-portable cluster size)
    cudaFuncSetAttribute((const void*)lstm_kernel,
                         cudaFuncAttributeNonPortableClusterSizeAllowed, 1);
    cudaLaunchConfig_t cfg = {};
    cfg.gridDim  = dim3(32, 1, 1);
    cfg.blockDim = dim3(384, 1, 1);
    cfg.dynamicSmemBytes = 0;
    cudaLaunchAttribute attrs[1];
    attrs[0].id = cudaLaunchAttributeClusterDimension;
    attrs[0].val.clusterDim.x = 16;
    attrs[0].val.clusterDim.y = 1;
    attrs[0].val.clusterDim.z = 1;
    cfg.attrs = attrs;
    cfg.numAttrs = 1;
    cudaLaunchKernelEx(&cfg, lstm_kernel, Whh_f, Whh_b);

    pool_kernel<<<NEV, 256>>>(lev);
    gemm_mlp1_kernel<<<dim3(12, 16), 256>>>(W1, b1);
    scores_kernel<<<NEV / 8, 256>>>(W2, b2, lev, scores_ptr);
    loss_reduce_kernel<<<1, 1024>>>(loss_ptr);
}

// round 5
// speedup vs baseline: 3.1809x; 1.4188x over previous
#include <cuda_runtime.h>
#include <cuda_bf16.h>
#include <cstdint>

typedef unsigned long long ull;

#define SQ   4096
#define DIM  768
#define HID  384
#define G4   1536
#define NEV  1024

// ---------------- static scratch (no runtime allocation) ----------------
__device__ float g_xw[2u * SQ * G4];    // permuted gate preactivations, both dirs
__device__ float g_tok[(size_t)SQ * DIM];
__device__ float g_emb[NEV * DIM];
__device__ float g_hidn[NEV * DIM];
__device__ float g_evloss[NEV];
__device__ float g_scores_scratch[2 * NEV];
__device__ float g_loss_scratch[1];

__device__ __forceinline__ float fast_sig(float x) {
    return __fdividef(1.0f, 1.0f + __expf(-x));
}
__device__ __forceinline__ float fast_tanh(float x) {
    return 1.0f - __fdividef(2.0f, __expf(2.0f * x) + 1.0f);
}

__device__ __forceinline__ unsigned smem_u32(const void* p) {
    unsigned a;
    asm("{ .reg .u64 t; cvta.to.shared.u64 t, %1; cvt.u32.u64 %0, t; }" : "=r"(a) : "l"(p));
    return a;
}

__device__ __forceinline__ void mbar_wait(unsigned mbar, unsigned parity) {
    unsigned done;
    asm volatile("{\n\t.reg .pred p;\n\t"
        "mbarrier.try_wait.parity.acquire.cluster.shared::cta.b64 p, [%1], %2;\n\t"
        "selp.b32 %0, 1, 0, p;\n\t}"
        : "=r"(done) : "r"(mbar), "r"(parity) : "memory");
    while (!done) {
        asm volatile("{\n\t.reg .pred p;\n\t"
            "mbarrier.try_wait.parity.acquire.cluster.shared::cta.b64 p, [%1], %2, 0x989680;\n\t"
            "selp.b32 %0, 1, 0, p;\n\t}"
            : "=r"(done) : "r"(mbar), "r"(parity) : "memory");
    }
}

__device__ __forceinline__ void mbar_expect(unsigned mbar, unsigned bytes) {
    asm volatile("mbarrier.arrive.expect_tx.shared.b64 _, [%0], %1;"
                 :: "r"(mbar), "r"(bytes) : "memory");
}

// ---------------------------------------------------------------------------
// GEMM A: xw[d][t][jj] = X[t] . W_d[orig(jj)] + (bih+bhh)[orig]
// column permutation: jj = cta*96 + gate*24 + u  <->  orig = gate*384 + cta*24 + u
// 64x64 tile, BK=32, 256 threads, 4x4/thread, packed fma.rn.f32x2
// ---------------------------------------------------------------------------
__global__ __launch_bounds__(256) void gemm_xw_kernel(
    const float* __restrict__ X,
    const float* __restrict__ Wf, const float* __restrict__ Wb,
    const float* __restrict__ bihf, const float* __restrict__ bhhf,
    const float* __restrict__ bihb, const float* __restrict__ bhhb)
{
    __shared__ float As[32][72];
    __shared__ float Bs[32][72];
    __shared__ const float* wptr[64];
    __shared__ float biasv[64];

    int tid = threadIdx.x;
    int bx = blockIdx.x, by = blockIdx.y;

    if (tid < 64) {
        int jp = bx * 64 + tid;          // 0..3071
        int d  = jp / G4;
        int jj = jp - d * G4;
        int cc = jj / 96, ll = jj % 96;
        int orig = (ll / 24) * HID + cc * 24 + (ll % 24);
        wptr[tid]  = (d ? Wb : Wf) + (size_t)orig * DIM;
        biasv[tid] = d ? (bihb[orig] + bhhb[orig]) : (bihf[orig] + bhhf[orig]);
    }
    __syncthreads();

    int tx = tid & 15, ty = tid >> 4;
    ull acc2[4][2];
    #pragma unroll
    for (int i = 0; i < 4; i++) { acc2[i][0] = 0ull; acc2[i][1] = 0ull; }

    for (int k0 = 0; k0 < DIM; k0 += 32) {
        #pragma unroll
        for (int i = 0; i < 2; i++) {
            int id = tid + i * 256;
            int r = id >> 3, c4 = id & 7;
            float4 v = *reinterpret_cast<const float4*>(X + (size_t)(by * 64 + r) * DIM + k0 + c4 * 4);
            As[c4*4+0][r] = v.x; As[c4*4+1][r] = v.y; As[c4*4+2][r] = v.z; As[c4*4+3][r] = v.w;
            float4 w = *reinterpret_cast<const float4*>(wptr[r] + k0 + c4 * 4);
            Bs[c4*4+0][r] = w.x; Bs[c4*4+1][r] = w.y; Bs[c4*4+2][r] = w.z; Bs[c4*4+3][r] = w.w;
        }
        __syncthreads();
        #pragma unroll
        for (int k = 0; k < 32; k++) {
            float4 av = *reinterpret_cast<const float4*>(&As[k][ty * 4]);
            ull b0 = *reinterpret_cast<const ull*>(&Bs[k][tx * 4]);
            ull b1 = *reinterpret_cast<const ull*>(&Bs[k][tx * 4 + 2]);
            float a_[4] = {av.x, av.y, av.z, av.w};
            #pragma unroll
            for (int i = 0; i < 4; i++) {
                ull ad;
                asm("mov.b64 %0, {%1, %1};" : "=l"(ad) : "f"(a_[i]));
                asm("fma.rn.f32x2 %0, %1, %2, %0;" : "+l"(acc2[i][0]) : "l"(ad), "l"(b0));
                asm("fma.rn.f32x2 %0, %1, %2, %0;" : "+l"(acc2[i][1]) : "l"(ad), "l"(b1));
            }
        }
        __syncthreads();
    }

    int d = (bx * 64) / G4;
    size_t outbase = (size_t)d * SQ * G4;
    int col0 = bx * 64 - d * G4 + tx * 4;
    #pragma unroll
    for (int i = 0; i < 4; i++) {
        int t = by * 64 + ty * 4 + i;
        float2 p0 = *reinterpret_cast<float2*>(&acc2[i][0]);
        float2 p1 = *reinterpret_cast<float2*>(&acc2[i][1]);
        float* o = g_xw + outbase + (size_t)t * G4 + col0;
        o[0] = p0.x + biasv[tx*4+0];
        o[1] = p0.y + biasv[tx*4+1];
        o[2] = p1.x + biasv[tx*4+2];
        o[3] = p1.y + biasv[tx*4+3];
    }
}

// ---------------------------------------------------------------------------
// LSTM: one 16-CTA cluster per direction. Weights register-resident
// (96 fp32/thread). h exchanged by st.async DSMEM push with per-CTA
// mbarrier tx-completion (1536 B = 384 floats per step per destination).
// No cluster barrier in the steady state; one __syncthreads per step.
// MAC role: rr = tid>>2 (row 0..95), q = tid&3 (96-wide k-chunk).
// Activation role: u = tid%24 (unit), peer = tid/24; c replicated 16x.
// Buffer-reuse safety is transitive: a producer reaching step t+2 has
// observed step-t+1 completions, which data-depend on every CTA's step-t
// reads (each CTA's intra-step __syncthreads orders all MAC/gate reads
// before any of its st.async stores).
// ---------------------------------------------------------------------------
__global__ __launch_bounds__(384, 1) void lstm_kernel(
    const float* __restrict__ Whh_f, const float* __restrict__ Whh_b)
{
    __shared__ __align__(16) float sh_h[2 * 400];   // [buf][chunk q at q*100]
    __shared__ float sh_gate[2][96];                // double-buffered by parity
    __shared__ __align__(8) ull sh_mbar[2];

    int tid = threadIdx.x;
    int dir = blockIdx.x >> 4;
    unsigned cta;
    asm("mov.u32 %0, %%cluster_ctarank;" : "=r"(cta));

    int rr = tid >> 2, q = tid & 3;
    int u = tid % 24, peer = tid / 24;
    int gate = rr / 24, uu = rr % 24;
    int orig = gate * HID + (int)cta * 24 + uu;

    const float* Whh = dir ? Whh_b : Whh_f;
    const ull* wrow = reinterpret_cast<const ull*>(Whh + (size_t)orig * HID + q * 96);
    ull wreg[48];
    #pragma unroll
    for (int j = 0; j < 48; j++) wreg[j] = wrow[j];

    // zero both h buffers
    for (int i = tid; i < 2 * 400; i += 384) sh_h[i] = 0.0f;

    unsigned mb0 = smem_u32(&sh_mbar[0]);
    unsigned mb1 = mb0 + 8;
    if (tid == 0) {
        asm volatile("mbarrier.init.shared.b64 [%0], 1;" :: "r"(mb0) : "memory");
        asm volatile("mbarrier.init.shared.b64 [%0], 1;" :: "r"(mb1) : "memory");
        mbar_expect(mb0, 1536);
        mbar_expect(mb1, 1536);
        asm volatile("fence.mbarrier_init.release.cluster;" ::: "memory");
    }
    __syncthreads();

    // DSMEM target addresses for my unit hidx in peer's buffers + mbarriers
    int hidx = (int)cta * 24 + u;
    int qq = hidx / 96, mm = hidx % 96;
    unsigned loc0 = smem_u32(&sh_h[qq * 100 + mm]);
    unsigned loc1 = loc0 + 400 * 4;
    unsigned rem0, rem1, remm0, remm1;
    asm("mapa.shared::cluster.u32 %0, %1, %2;" : "=r"(rem0)  : "r"(loc0), "r"(peer));
    asm("mapa.shared::cluster.u32 %0, %1, %2;" : "=r"(rem1)  : "r"(loc1), "r"(peer));
    asm("mapa.shared::cluster.u32 %0, %1, %2;" : "=r"(remm0) : "r"(mb0),  "r"(peer));
    asm("mapa.shared::cluster.u32 %0, %1, %2;" : "=r"(remm1) : "r"(mb1),  "r"(peer));

    // all buffers zeroed + mbarriers initialized cluster-wide
    asm volatile("barrier.cluster.arrive.aligned;" ::: "memory");
    asm volatile("barrier.cluster.wait.aligned;"   ::: "memory");

    const float* xwp = g_xw + (size_t)dir * SQ * G4 + (size_t)cta * 96 + rr;
    float c_reg = 0.0f;
    float xw_cur = (q == 0) ? __ldcg(xwp + (size_t)(dir ? SQ - 1 : 0) * G4) : 0.0f;
    unsigned ph0 = 0, ph1 = 0;

    for (int t = 0; t < SQ; t++) {
        int par = t & 1;

        // prefetch next step's xw before the wait (overlaps mbar wait)
        float xw_next = 0.0f;
        if (q == 0 && t + 1 < SQ) {
            int tn = dir ? (SQ - 2 - t) : (t + 1);
            xw_next = __ldcg(xwp + (size_t)tn * G4);
        }

        // wait for this step's h buffer (t=0 consumes zeros, no wait)
        if (t > 0) {
            if (par) { mbar_wait(mb1, ph1); ph1 ^= 1; if (tid == 0) mbar_expect(mb1, 1536); }
            else     { mbar_wait(mb0, ph0); ph0 ^= 1; if (tid == 0) mbar_expect(mb0, 1536); }
        }

        // MAC: this row's 96-element k-chunk of h
        const ulonglong2* hp2 =
            reinterpret_cast<const ulonglong2*>(sh_h + par * 400 + q * 100);
        ull a0 = 0ull, a1 = 0ull, a2 = 0ull, a3 = 0ull;
        #pragma unroll
        for (int j = 0; j < 12; j++) {
            ulonglong2 x0 = hp2[2 * j];
            ulonglong2 x1 = hp2[2 * j + 1];
            asm("fma.rn.f32x2 %0, %1, %2, %0;" : "+l"(a0) : "l"(wreg[4*j+0]), "l"(x0.x));
            asm("fma.rn.f32x2 %0, %1, %2, %0;" : "+l"(a1) : "l"(wreg[4*j+1]), "l"(x0.y));
            asm("fma.rn.f32x2 %0, %1, %2, %0;" : "+l"(a2) : "l"(wreg[4*j+2]), "l"(x1.x));
            asm("fma.rn.f32x2 %0, %1, %2, %0;" : "+l"(a3) : "l"(wreg[4*j+3]), "l"(x1.y));
        }
        asm("add.rn.f32x2 %0, %0, %1;" : "+l"(a0) : "l"(a1));
        asm("add.rn.f32x2 %0, %0, %1;" : "+l"(a2) : "l"(a3));
        asm("add.rn.f32x2 %0, %0, %1;" : "+l"(a0) : "l"(a2));
        float lo, hi;
        asm("mov.b64 {%0, %1}, %2;" : "=f"(lo), "=f"(hi) : "l"(a0));
        float s = lo + hi;
        s += __shfl_xor_sync(0xffffffffu, s, 1);
        s += __shfl_xor_sync(0xffffffffu, s, 2);
        if (q == 0) sh_gate[par][rr] = s + xw_cur;
        __syncthreads();   // orders ALL h/gate reads before any store below

        // activation (replicated across the 16 peer-groups, deterministic)
        float gi = sh_gate[par][u],      gf = sh_gate[par][24 + u];
        float gg = sh_gate[par][48 + u], go = sh_gate[par][72 + u];
        float cf = fast_sig(gf) * c_reg + fast_sig(gi) * fast_tanh(gg);
        c_reg = cf;
        float hv = fast_sig(go) * fast_tanh(cf);

        // push my unit's h into peer's buf[(t+1)&1] with tx completion
        if (t + 1 < SQ) {
            unsigned rem  = par ? rem0  : rem1;
            unsigned remm = par ? remm0 : remm1;
            asm volatile("st.async.shared::cluster.mbarrier::complete_tx::bytes.b32 [%0], %1, [%2];"
                         :: "r"(rem), "r"(__float_as_uint(hv)), "r"(remm) : "memory");
        }

        if (peer == 0) {
            int tt = dir ? (SQ - 1 - t) : t;
            g_tok[(size_t)tt * DIM + dir * HID + hidx] = hv;
        }

        xw_cur = xw_next;
    }

    // keep SMEM alive until all cluster CTAs are done
    asm volatile("barrier.cluster.arrive.aligned;" ::: "memory");
    asm volatile("barrier.cluster.wait.aligned;"   ::: "memory");
}

// ---------------------------------------------------------------------------
// Event mean-pool: one CTA per event
// ---------------------------------------------------------------------------
__global__ __launch_bounds__(256) void pool_kernel(const int* __restrict__ label_event)
{
    int e = blockIdx.x;
    int start = label_event[e * 3 + 0];
    int end   = label_event[e * 3 + 1];
    float inv = 1.0f / (float)(end - start);
    for (int c = threadIdx.x; c < DIM; c += 256) {
        float s = 0.0f;
        for (int r = start; r < end; r++) s += g_tok[(size_t)r * DIM + c];
        g_emb[(size_t)e * DIM + c] = s * inv;
    }
}

// ---------------------------------------------------------------------------
// MLP layer 1: hid = relu(emb @ W1^T + b1)   [1024 x 768] x [768 x 768]
// ---------------------------------------------------------------------------
__global__ __launch_bounds__(256) void gemm_mlp1_kernel(
    const float* __restrict__ W1, const float* __restrict__ b1)
{
    __shared__ float As[32][72];
    __shared__ float Bs[32][72];

    int tid = threadIdx.x;
    int bx = blockIdx.x, by = blockIdx.y;
    int tx = tid & 15, ty = tid >> 4;

    ull acc2[4][2];
    #pragma unroll
    for (int i = 0; i < 4; i++) { acc2[i][0] = 0ull; acc2[i][1] = 0ull; }

    for (int k0 = 0; k0 < DIM; k0 += 32) {
        #pragma unroll
        for (int i = 0; i < 2; i++) {
            int id = tid + i * 256;
            int r = id >> 3, c4 = id & 7;
            float4 v = *reinterpret_cast<const float4*>(g_emb + (size_t)(by * 64 + r) * DIM + k0 + c4 * 4);
            As[c4*4+0][r] = v.x; As[c4*4+1][r] = v.y; As[c4*4+2][r] = v.z; As[c4*4+3][r] = v.w;
            float4 w = *reinterpret_cast<const float4*>(W1 + (size_t)(bx * 64 + r) * DIM + k0 + c4 * 4);
            Bs[c4*4+0][r] = w.x; Bs[c4*4+1][r] = w.y; Bs[c4*4+2][r] = w.z; Bs[c4*4+3][r] = w.w;
        }
        __syncthreads();
        #pragma unroll
        for (int k = 0; k < 32; k++) {
            float4 av = *reinterpret_cast<const float4*>(&As[k][ty * 4]);
            ull b0 = *reinterpret_cast<const ull*>(&Bs[k][tx * 4]);
            ull b1v = *reinterpret_cast<const ull*>(&Bs[k][tx * 4 + 2]);
            float a_[4] = {av.x, av.y, av.z, av.w};
            #pragma unroll
            for (int i = 0; i < 4; i++) {
                ull ad;
                asm("mov.b64 %0, {%1, %1};" : "=l"(ad) : "f"(a_[i]));
                asm("fma.rn.f32x2 %0, %1, %2, %0;" : "+l"(acc2[i][0]) : "l"(ad), "l"(b0));
                asm("fma.rn.f32x2 %0, %1, %2, %0;" : "+l"(acc2[i][1]) : "l"(ad), "l"(b1v));
            }
        }
        __syncthreads();
    }

    int col0 = bx * 64 + tx * 4;
    #pragma unroll
    for (int i = 0; i < 4; i++) {
        int row = by * 64 + ty * 4 + i;
        float2 p0 = *reinterpret_cast<float2*>(&acc2[i][0]);
        float2 p1 = *reinterpret_cast<float2*>(&acc2[i][1]);
        float* o = g_hidn + (size_t)row * DIM + col0;
        o[0] = fmaxf(p0.x + b1[col0 + 0], 0.0f);
        o[1] = fmaxf(p0.y + b1[col0 + 1], 0.0f);
        o[2] = fmaxf(p1.x + b1[col0 + 2], 0.0f);
        o[3] = fmaxf(p1.y + b1[col0 + 3], 0.0f);
    }
}

// ---------------------------------------------------------------------------
// Layer 2 + log-softmax + weighted CE per event. One warp per event.
// ---------------------------------------------------------------------------
__global__ __launch_bounds__(256) void scores_kernel(
    const float* __restrict__ W2, const float* __restrict__ b2,
    const int* __restrict__ label_event, float* scores_out)
{
    int lane = threadIdx.x & 31;
    int w = threadIdx.x >> 5;
    int e = blockIdx.x * 8 + w;
    const float* hrow = g_hidn + (size_t)e * DIM;

    float s0 = 0.0f, s1 = 0.0f;
    #pragma unroll
    for (int k = 0; k < 24; k++) {
        float v = hrow[lane + 32 * k];
        s0 += v * __ldg(&W2[lane + 32 * k]);
        s1 += v * __ldg(&W2[DIM + lane + 32 * k]);
    }
    #pragma unroll
    for (int m = 16; m >= 1; m >>= 1) {
        s0 += __shfl_xor_sync(0xffffffffu, s0, m);
        s1 += __shfl_xor_sync(0xffffffffu, s1, m);
    }
    if (lane == 0) {
        s0 += b2[0]; s1 += b2[1];
        float* sp = scores_out ? scores_out : g_scores_scratch;
        sp[2 * e + 0] = s0;
        sp[2 * e + 1] = s1;
        float mx = fmaxf(s0, s1);
        float lse = mx + logf(expf(s0 - mx) + expf(s1 - mx));
        int lab = label_event[e * 3 + 2];
        float sl = lab ? s1 : s0;
        float ce = lse - sl;
        float wgt = (lab == 0) ? 1.0f : (float)lab * 1.0f;
        g_evloss[e] = ce * wgt;
    }
}

__global__ __launch_bounds__(1024) void loss_reduce_kernel(float* loss_out)
{
    __shared__ float red[1024];
    int tid = threadIdx.x;
    red[tid] = g_evloss[tid];
    __syncthreads();
    for (int s = 512; s >= 1; s >>= 1) {
        if (tid < s) red[tid] += red[tid + s];
        __syncthreads();
    }
    if (tid == 0) {
        float* lp = loss_out ? loss_out : g_loss_scratch;
        lp[0] = red[0];
    }
}

// ---------------------------------------------------------------------------
extern "C" void kernel_launch(void* const* d_in, const int* in_sizes, int n_in,
                              void* d_out, int out_size) {
    const float* X     = (const float*)d_in[0];
    const int*   lev   = (const int*)  d_in[1];
    const float* Wih_f = (const float*)d_in[2];
    const float* Whh_f = (const float*)d_in[3];
    const float* bih_f = (const float*)d_in[4];
    const float* bhh_f = (const float*)d_in[5];
    const float* Wih_b = (const float*)d_in[6];
    const float* Whh_b = (const float*)d_in[7];
    const float* bih_b = (const float*)d_in[8];
    const float* bhh_b = (const float*)d_in[9];
    const float* W1    = (const float*)d_in[10];
    const float* b1    = (const float*)d_in[11];
    const float* W2    = (const float*)d_in[12];
    const float* b2    = (const float*)d_in[13];

    float* out = (float*)d_out;
    float* loss_ptr   = nullptr;
    float* scores_ptr = nullptr;
    if (out_size >= 2049)      { loss_ptr = out; scores_ptr = out + 1; }
    else if (out_size >= 2048) { scores_ptr = out; }
    else                       { loss_ptr = out; }

    gemm_xw_kernel<<<dim3(48, 64), 256>>>(X, Wih_f, Wih_b, bih_f, bhh_f, bih_b, bhh_b);

    // LSTM: 2 clusters of 16 CTAs (non-portable cluster size)
    cudaFuncSetAttribute((const void*)lstm_kernel,
                         cudaFuncAttributeNonPortableClusterSizeAllowed, 1);
    cudaLaunchConfig_t cfg = {};
    cfg.gridDim  = dim3(32, 1, 1);
    cfg.blockDim = dim3(384, 1, 1);
    cfg.dynamicSmemBytes = 0;
    cudaLaunchAttribute attrs[1];
    attrs[0].id = cudaLaunchAttributeClusterDimension;
    attrs[0].val.clusterDim.x = 16;
    attrs[0].val.clusterDim.y = 1;
    attrs[0].val.clusterDim.z = 1;
    cfg.attrs = attrs;
    cfg.numAttrs = 1;
    cudaLaunchKernelEx(&cfg, lstm_kernel, Whh_f, Whh_b);

    pool_kernel<<<NEV, 256>>>(lev);
    gemm_mlp1_kernel<<<dim3(12, 16), 256>>>(W1, b1);
    scores_kernel<<<NEV / 8, 256>>>(W2, b2, lev, scores_ptr);
    loss_reduce_kernel<<<1, 1024>>>(loss_ptr);
}